// round 12
// baseline (speedup 1.0000x reference)
#include <cuda_runtime.h>
#include <math.h>

// Problem constants (fixed by reference)
#define VOCAB 100000
#define DIM   128
#define BATCH 16384
#define CTX   10
#define NEG   5

#define WARPS_PER_BLOCK 8
#define THREADS (WARPS_PER_BLOCK * 32)
#define NUM_BLOCKS 1184        // 148 SMs x 8 CTAs: exactly one wave, 64 warps/SM
#define WCHUNK 2               // elements per warp grab

// Scratch (no cudaMalloc allowed)
__device__ double       g_accum  = 0.0;
__device__ unsigned int g_ticket = 0;
__device__ unsigned int g_work   = 0;

__device__ __forceinline__ float log_sigmoid(float x) {
    // stable: min(x,0) - log1p(exp(-|x|))
    return fminf(x, 0.0f) - log1pf(expf(-fabsf(x)));
}

// Asymmetric L2 policy (R6 measured-best): pin u-table, stream w-table.
__device__ __forceinline__ unsigned long long make_policy_keep() {
    unsigned long long pol;
    asm("createpolicy.fractional.L2::evict_last.b64 %0, 1.0;" : "=l"(pol));
    return pol;
}
__device__ __forceinline__ unsigned long long make_policy_stream() {
    unsigned long long pol;
    asm("createpolicy.fractional.L2::evict_first.b64 %0, 1.0;" : "=l"(pol));
    return pol;
}
__device__ __forceinline__ float4 ldg_pol(const float4* p, unsigned long long pol) {
    float4 v;
    asm("ld.global.nc.L2::cache_hint.v4.f32 {%0,%1,%2,%3}, [%4], %5;"
        : "=f"(v.x), "=f"(v.y), "=f"(v.z), "=f"(v.w)
        : "l"(p), "l"(pol));
    return v;
}

__global__ __launch_bounds__(THREADS)
void cbow_loss_fused(const int* __restrict__ pos_u,   // [B, CTX]
                     const int* __restrict__ pos_w,   // [B]
                     const int* __restrict__ neg_w,   // [B, NEG]
                     const float4* __restrict__ u_w,  // [VOCAB, 32] as float4
                     const float4* __restrict__ w_w,  // [VOCAB, 32] as float4
                     float* __restrict__ out)
{
    const int warp = threadIdx.x >> 5;
    const int lane = threadIdx.x & 31;

    const unsigned long long pol_keep   = make_policy_keep();
    const unsigned long long pol_stream = make_policy_stream();

    float ls = 0.0f;   // lane0 accumulates logsigmoid terms across rounds

    // --- per-warp work stealing: NO barriers in the mainloop ---
    for (;;) {
        unsigned base = 0;
        if (lane == 0)
            base = atomicAdd(&g_work, (unsigned)WCHUNK);
        base = __shfl_sync(0xFFFFFFFFu, base, 0);
        if (base >= BATCH) break;

        #pragma unroll
        for (int e = 0; e < WCHUNK; ++e) {
            const int b = (int)base + e;       // BATCH % WCHUNK == 0: always valid

            // --- gather-sum context embeddings (u-table: keep) ---
            float4 usum = make_float4(0.f, 0.f, 0.f, 0.f);
            const int* pu = pos_u + b * CTX;
            #pragma unroll
            for (int c = 0; c < CTX; ++c) {
                int idx = __ldg(pu + c);                 // uniform across warp
                float4 v = ldg_pol(u_w + (size_t)idx * 32 + lane, pol_keep);
                usum.x += v.x; usum.y += v.y; usum.z += v.z; usum.w += v.w;
            }

            // --- positive target row (w-table: stream) ---
            int pidx = __ldg(pos_w + b);
            float4 p = ldg_pol(w_w + (size_t)pidx * 32 + lane, pol_stream);
            float pd = usum.x * p.x + usum.y * p.y + usum.z * p.z + usum.w * p.w;

            // --- negative rows summed first (dot distributes over the sum) ---
            float4 nsum = make_float4(0.f, 0.f, 0.f, 0.f);
            const int* nw = neg_w + b * NEG;
            #pragma unroll
            for (int k = 0; k < NEG; ++k) {
                int idx = __ldg(nw + k);
                float4 v = ldg_pol(w_w + (size_t)idx * 32 + lane, pol_stream);
                nsum.x += v.x; nsum.y += v.y; nsum.z += v.z; nsum.w += v.w;
            }
            float nd = usum.x * nsum.x + usum.y * nsum.y + usum.z * nsum.z + usum.w * nsum.w;

            // --- warp reduce both dots together ---
            #pragma unroll
            for (int off = 16; off > 0; off >>= 1) {
                pd += __shfl_xor_sync(0xFFFFFFFFu, pd, off);
                nd += __shfl_xor_sync(0xFFFFFFFFu, nd, off);
            }
            if (lane == 0)
                ls += log_sigmoid(pd) + log_sigmoid(-nd);
        }
    }

    __shared__ float s_part[WARPS_PER_BLOCK];
    if (lane == 0)
        s_part[warp] = ls;
    __syncthreads();   // single barrier, after all work

    // --- featherweight epilogue: one double atomic per block + ticket ---
    if (threadIdx.x == 0) {
        float acc = 0.f;
        #pragma unroll
        for (int i = 0; i < WARPS_PER_BLOCK; ++i) acc += s_part[i];
        atomicAdd(&g_accum, (double)acc);   // order-insensitive in double
        __threadfence();                    // release before ticket
        unsigned int t = atomicAdd(&g_ticket, 1u);
        if (t == NUM_BLOCKS - 1) {
            __threadfence();                // acquire after last ticket
            double total = g_accum;
            out[0] = (float)(-total);       // loss = -(sum of logsigmoids)
            g_accum  = 0.0;                 // reset for next graph replay
            g_ticket = 0;
            g_work   = 0;                   // all grabs done before last ticket
        }
    }
}

extern "C" void kernel_launch(void* const* d_in, const int* in_sizes, int n_in,
                              void* d_out, int out_size) {
    const int*    pos_u = (const int*)d_in[0];
    const int*    pos_w = (const int*)d_in[1];
    const int*    neg_w = (const int*)d_in[2];
    const float4* u_w   = (const float4*)d_in[3];
    const float4* w_w   = (const float4*)d_in[4];
    float* out = (float*)d_out;

    cbow_loss_fused<<<NUM_BLOCKS, THREADS>>>(pos_u, pos_w, neg_w, u_w, w_w, out);
}

// round 13
// speedup vs baseline: 1.5379x; 1.5379x over previous
#include <cuda_runtime.h>
#include <math.h>

// Problem constants (fixed by reference)
#define VOCAB 100000
#define DIM   128
#define BATCH 16384
#define CTX   10
#define NEG   5

#define WARPS_PER_BLOCK 8
#define THREADS (WARPS_PER_BLOCK * 32)
#define NUM_BLOCKS 1184                        // 148 SMs x 8 CTAs exactly
#define TOTAL_WARPS (NUM_BLOCKS * WARPS_PER_BLOCK)   // 9472
#define EXTRAS (BATCH - TOTAL_WARPS)                 // 6912 second elements

// Scratch (no cudaMalloc allowed)
__device__ double       g_accum  = 0.0;
__device__ unsigned int g_ticket = 0;

__device__ __forceinline__ float log_sigmoid(float x) {
    // stable: min(x,0) - log1p(exp(-|x|))
    return fminf(x, 0.0f) - log1pf(expf(-fabsf(x)));
}

// Asymmetric L2 policy (measured-best): pin u-table, stream w-table.
__device__ __forceinline__ unsigned long long make_policy_keep() {
    unsigned long long pol;
    asm("createpolicy.fractional.L2::evict_last.b64 %0, 1.0;" : "=l"(pol));
    return pol;
}
__device__ __forceinline__ unsigned long long make_policy_stream() {
    unsigned long long pol;
    asm("createpolicy.fractional.L2::evict_first.b64 %0, 1.0;" : "=l"(pol));
    return pol;
}
__device__ __forceinline__ float4 ldg_pol(const float4* p, unsigned long long pol) {
    float4 v;
    asm("ld.global.nc.L2::cache_hint.v4.f32 {%0,%1,%2,%3}, [%4], %5;"
        : "=f"(v.x), "=f"(v.y), "=f"(v.z), "=f"(v.w)
        : "l"(p), "l"(pol));
    return v;
}

// One batch element, R6 body verbatim. Returns logsigmoid(pd)+logsigmoid(-nd) on lane0.
__device__ __forceinline__ float process_elem(
    int b, int lane,
    const int* __restrict__ pos_u, const int* __restrict__ pos_w,
    const int* __restrict__ neg_w,
    const float4* __restrict__ u_w, const float4* __restrict__ w_w,
    unsigned long long pol_keep, unsigned long long pol_stream)
{
    // --- gather-sum context embeddings (u-table: keep) ---
    float4 usum = make_float4(0.f, 0.f, 0.f, 0.f);
    const int* pu = pos_u + b * CTX;
    #pragma unroll
    for (int c = 0; c < CTX; ++c) {
        int idx = __ldg(pu + c);                     // uniform across warp
        float4 v = ldg_pol(u_w + (size_t)idx * 32 + lane, pol_keep);
        usum.x += v.x; usum.y += v.y; usum.z += v.z; usum.w += v.w;
    }

    // --- positive target row (w-table: stream) ---
    int pidx = __ldg(pos_w + b);
    float4 p = ldg_pol(w_w + (size_t)pidx * 32 + lane, pol_stream);
    float pd = usum.x * p.x + usum.y * p.y + usum.z * p.z + usum.w * p.w;

    // --- negative rows summed first (dot distributes over the sum) ---
    float4 nsum = make_float4(0.f, 0.f, 0.f, 0.f);
    const int* nw = neg_w + b * NEG;
    #pragma unroll
    for (int k = 0; k < NEG; ++k) {
        int idx = __ldg(nw + k);
        float4 v = ldg_pol(w_w + (size_t)idx * 32 + lane, pol_stream);
        nsum.x += v.x; nsum.y += v.y; nsum.z += v.z; nsum.w += v.w;
    }
    float nd = usum.x * nsum.x + usum.y * nsum.y + usum.z * nsum.z + usum.w * nsum.w;

    // --- warp reduce both dots together ---
    #pragma unroll
    for (int off = 16; off > 0; off >>= 1) {
        pd += __shfl_xor_sync(0xFFFFFFFFu, pd, off);
        nd += __shfl_xor_sync(0xFFFFFFFFu, nd, off);
    }
    return log_sigmoid(pd) + log_sigmoid(-nd);   // meaningful on lane 0
}

__global__ __launch_bounds__(THREADS)
void cbow_loss_fused(const int* __restrict__ pos_u,   // [B, CTX]
                     const int* __restrict__ pos_w,   // [B]
                     const int* __restrict__ neg_w,   // [B, NEG]
                     const float4* __restrict__ u_w,  // [VOCAB, 32] as float4
                     const float4* __restrict__ w_w,  // [VOCAB, 32] as float4
                     float* __restrict__ out)
{
    const int warp = threadIdx.x >> 5;
    const int lane = threadIdx.x & 31;
    const int wgid = blockIdx.x * WARPS_PER_BLOCK + warp;   // 0..9471

    const unsigned long long pol_keep   = make_policy_keep();
    const unsigned long long pol_stream = make_policy_stream();

    float ls = 0.0f;

    // Element 1: every warp
    ls += process_elem(wgid, lane, pos_u, pos_w, neg_w, u_w, w_w,
                       pol_keep, pol_stream);

    // Element 2: Bresenham-distributed extras (even across SMs, no atomics)
    // warp w gets an extra iff floor((w+1)*E/T) > floor(w*E/T)
    const int lo = (int)(((long long)wgid * EXTRAS) / TOTAL_WARPS);
    const int hi = (int)(((long long)(wgid + 1) * EXTRAS) / TOTAL_WARPS);
    if (hi > lo) {
        ls += process_elem(TOTAL_WARPS + lo, lane, pos_u, pos_w, neg_w, u_w, w_w,
                           pol_keep, pol_stream);
    }

    __shared__ float s_part[WARPS_PER_BLOCK];
    if (lane == 0)
        s_part[warp] = ls;
    __syncthreads();   // single barrier, after all work

    // --- featherweight epilogue: one double atomic per block + ticket ---
    if (threadIdx.x == 0) {
        float acc = 0.f;
        #pragma unroll
        for (int i = 0; i < WARPS_PER_BLOCK; ++i) acc += s_part[i];
        atomicAdd(&g_accum, (double)acc);   // order-insensitive in double
        __threadfence();                    // release before ticket
        unsigned int t = atomicAdd(&g_ticket, 1u);
        if (t == NUM_BLOCKS - 1) {
            __threadfence();                // acquire after last ticket
            double total = g_accum;
            out[0] = (float)(-total);       // loss = -(sum of logsigmoids)
            g_accum  = 0.0;                 // reset for next graph replay
            g_ticket = 0;
        }
    }
}

extern "C" void kernel_launch(void* const* d_in, const int* in_sizes, int n_in,
                              void* d_out, int out_size) {
    const int*    pos_u = (const int*)d_in[0];
    const int*    pos_w = (const int*)d_in[1];
    const int*    neg_w = (const int*)d_in[2];
    const float4* u_w   = (const float4*)d_in[3];
    const float4* w_w   = (const float4*)d_in[4];
    float* out = (float*)d_out;

    cbow_loss_fused<<<NUM_BLOCKS, THREADS>>>(pos_u, pos_w, neg_w, u_w, w_w, out);
}

// round 14
// speedup vs baseline: 1.6815x; 1.0934x over previous
#include <cuda_runtime.h>
#include <math.h>

// Problem constants (fixed by reference)
#define VOCAB 100000
#define DIM   128
#define BATCH 16384
#define CTX   10
#define NEG   5

#define WARPS_PER_BLOCK 8
#define THREADS (WARPS_PER_BLOCK * 32)
#define ELEMS_PER_WARP 2
#define NUM_BLOCKS (BATCH / (WARPS_PER_BLOCK * ELEMS_PER_WARP))   // 1024

// Scratch (no cudaMalloc allowed)
__device__ double       g_accum  = 0.0;
__device__ unsigned int g_ticket = 0;

__device__ __forceinline__ float log_sigmoid(float x) {
    // stable: min(x,0) - log1p(exp(-|x|))
    return fminf(x, 0.0f) - log1pf(expf(-fabsf(x)));
}

// Asymmetric L2 policy (measured-best): pin u-table, stream w-table.
__device__ __forceinline__ unsigned long long make_policy_keep() {
    unsigned long long pol;
    asm("createpolicy.fractional.L2::evict_last.b64 %0, 1.0;" : "=l"(pol));
    return pol;
}
__device__ __forceinline__ unsigned long long make_policy_stream() {
    unsigned long long pol;
    asm("createpolicy.fractional.L2::evict_first.b64 %0, 1.0;" : "=l"(pol));
    return pol;
}
// Row loads: .cg = cache at L2 ONLY. Rows have ~zero L1 reuse (random gather),
// so L1 allocation is pure overhead in the L1tex wavefront queue. Keep the L2
// eviction-policy hint.
__device__ __forceinline__ float4 ldg_cg_pol(const float4* p, unsigned long long pol) {
    float4 v;
    asm("ld.global.cg.L2::cache_hint.v4.f32 {%0,%1,%2,%3}, [%4], %5;"
        : "=f"(v.x), "=f"(v.y), "=f"(v.z), "=f"(v.w)
        : "l"(p), "l"(pol));
    return v;
}

__global__ __launch_bounds__(THREADS)
void cbow_loss_fused(const int* __restrict__ pos_u,   // [B, CTX]
                     const int* __restrict__ pos_w,   // [B]
                     const int* __restrict__ neg_w,   // [B, NEG]
                     const float4* __restrict__ u_w,  // [VOCAB, 32] as float4
                     const float4* __restrict__ w_w,  // [VOCAB, 32] as float4
                     float* __restrict__ out)
{
    const int warp = threadIdx.x >> 5;
    const int lane = threadIdx.x & 31;
    const int b0 = (blockIdx.x * WARPS_PER_BLOCK + warp) * ELEMS_PER_WARP;

    const unsigned long long pol_keep   = make_policy_keep();
    const unsigned long long pol_stream = make_policy_stream();

    float ls = 0.0f;   // lane0 accumulates logsigmoid terms

    #pragma unroll
    for (int e = 0; e < ELEMS_PER_WARP; ++e) {
        const int b = b0 + e;

        // --- gather-sum context embeddings (u-table: keep, L2-only) ---
        float4 usum = make_float4(0.f, 0.f, 0.f, 0.f);
        const int* pu = pos_u + b * CTX;
        #pragma unroll
        for (int c = 0; c < CTX; ++c) {
            int idx = __ldg(pu + c);                     // uniform across warp (L1-friendly)
            float4 v = ldg_cg_pol(u_w + (size_t)idx * 32 + lane, pol_keep);
            usum.x += v.x; usum.y += v.y; usum.z += v.z; usum.w += v.w;
        }

        // --- positive target row (w-table: stream, L2-only) ---
        int pidx = __ldg(pos_w + b);
        float4 p = ldg_cg_pol(w_w + (size_t)pidx * 32 + lane, pol_stream);
        float pd = usum.x * p.x + usum.y * p.y + usum.z * p.z + usum.w * p.w;

        // --- negative rows summed first (dot distributes over the sum) ---
        float4 nsum = make_float4(0.f, 0.f, 0.f, 0.f);
        const int* nw = neg_w + b * NEG;
        #pragma unroll
        for (int k = 0; k < NEG; ++k) {
            int idx = __ldg(nw + k);
            float4 v = ldg_cg_pol(w_w + (size_t)idx * 32 + lane, pol_stream);
            nsum.x += v.x; nsum.y += v.y; nsum.z += v.z; nsum.w += v.w;
        }
        float nd = usum.x * nsum.x + usum.y * nsum.y + usum.z * nsum.z + usum.w * nsum.w;

        // --- warp reduce both dots together ---
        #pragma unroll
        for (int off = 16; off > 0; off >>= 1) {
            pd += __shfl_xor_sync(0xFFFFFFFFu, pd, off);
            nd += __shfl_xor_sync(0xFFFFFFFFu, nd, off);
        }
        if (lane == 0)
            ls += log_sigmoid(pd) + log_sigmoid(-nd);
    }

    __shared__ float s_part[WARPS_PER_BLOCK];
    if (lane == 0)
        s_part[warp] = ls;
    __syncthreads();

    // --- featherweight epilogue: one double atomic per block + ticket ---
    if (threadIdx.x == 0) {
        float acc = 0.f;
        #pragma unroll
        for (int i = 0; i < WARPS_PER_BLOCK; ++i) acc += s_part[i];
        atomicAdd(&g_accum, (double)acc);   // order-insensitive in double
        __threadfence();                    // release before ticket
        unsigned int t = atomicAdd(&g_ticket, 1u);
        if (t == NUM_BLOCKS - 1) {
            __threadfence();                // acquire after last ticket
            double total = g_accum;
            out[0] = (float)(-total);       // loss = -(sum of logsigmoids)
            g_accum  = 0.0;                 // reset for next graph replay
            g_ticket = 0;
        }
    }
}

extern "C" void kernel_launch(void* const* d_in, const int* in_sizes, int n_in,
                              void* d_out, int out_size) {
    const int*    pos_u = (const int*)d_in[0];
    const int*    pos_w = (const int*)d_in[1];
    const int*    neg_w = (const int*)d_in[2];
    const float4* u_w   = (const float4*)d_in[3];
    const float4* w_w   = (const float4*)d_in[4];
    float* out = (float*)d_out;

    cbow_loss_fused<<<NUM_BLOCKS, THREADS>>>(pos_u, pos_w, neg_w, u_w, w_w, out);
}